// round 3
// baseline (speedup 1.0000x reference)
#include <cuda_runtime.h>
#include <cstdint>

// Chamfer loss, fused single kernel. B=16, N=4096, C=6 (first 3 used).
// d(i,j) = |q_i|^2 + [ |r_j|^2 - 2 q_i . r_j ]
// Ref tile prescaled to (-2r0,-2r1,-2r2,|r|^2): 3 packed FFMA2 per 2 pairs.
// Last CTA (arrival counter) finalizes: out = g_acc / (B*N), resets globals.

#define BATCH 16
#define NPTS  4096
#define CSTR  6
#define THREADS 256
#define IPT 4             // query points per thread
#define JT  2048          // ref points per smem tile
#define J2  (JT / 2)
#define GRID 128          // 2*16*4096 / (THREADS*IPT) -> one CTA per SM, single wave

__device__ float        g_acc;    // zero-init; reset by last CTA each launch
__device__ unsigned int g_count;  // zero-init; reset by last CTA each launch

__device__ __forceinline__ unsigned long long pk2(float lo, float hi) {
    unsigned long long r;
    asm("mov.b64 %0, {%1, %2};" : "=l"(r) : "f"(lo), "f"(hi));
    return r;
}
__device__ __forceinline__ unsigned long long fma2(unsigned long long a,
                                                   unsigned long long b,
                                                   unsigned long long c) {
    unsigned long long d;
    asm("fma.rn.f32x2 %0, %1, %2, %3;" : "=l"(d) : "l"(a), "l"(b), "l"(c));
    return d;
}
__device__ __forceinline__ void upk2(unsigned long long v, float& lo, float& hi) {
    asm("mov.b64 {%0, %1}, %2;" : "=f"(lo), "=f"(hi) : "l"(v));
}

__global__ void __launch_bounds__(THREADS)
k_chamfer(const float* __restrict__ x, const float* __restrict__ y,
          float* __restrict__ out) {
    __shared__ ulonglong2 s_a[J2];   // {-2rx pair}, {-2ry pair}
    __shared__ ulonglong2 s_b[J2];   // {-2rz pair}, {rr pair}
    __shared__ float ws[THREADS / 32];

    const int bid  = blockIdx.x;      // 0..127
    const int dir  = bid >> 6;        // 0: q=x,r=y ; 1: q=y,r=x
    const int t    = bid & 63;
    const int b    = t >> 2;          // batch
    const int tile = t & 3;           // i-tile (4 tiles of 1024 queries)

    const float* q  = dir ? y : x;
    const float* r  = dir ? x : y;
    const float* qb = q + (size_t)b * NPTS * CSTR;
    const float* rb = r + (size_t)b * NPTS * CSTR;

    const int tid = threadIdx.x;

    unsigned long long qx2[IPT], qy2[IPT], qz2[IPT];
    float rq[IPT], mnl[IPT], mnh[IPT];
    const int i0 = tile * (THREADS * IPT) + tid * IPT;
#pragma unroll
    for (int k = 0; k < IPT; k++) {
        const float* p = qb + (size_t)(i0 + k) * CSTR;
        float a = p[0], bb = p[1], c = p[2];
        rq[k]  = fmaf(a, a, fmaf(bb, bb, c * c));
        qx2[k] = pk2(a, a);
        qy2[k] = pk2(bb, bb);
        qz2[k] = pk2(c, c);
        mnl[k] = 3.4e38f;
        mnh[k] = 3.4e38f;
    }

    for (int jc = 0; jc < NPTS; jc += JT) {
        __syncthreads();
        for (int j = tid; j < J2; j += THREADS) {
            const float* p = rb + (size_t)(jc + 2 * j) * CSTR;
            float a0 = p[0], b0 = p[1], c0 = p[2];
            float a1 = p[6], b1 = p[7], c1 = p[8];
            float rr0 = fmaf(a0, a0, fmaf(b0, b0, c0 * c0));
            float rr1 = fmaf(a1, a1, fmaf(b1, b1, c1 * c1));
            ulonglong2 va, vb;
            va.x = pk2(-2.0f * a0, -2.0f * a1);
            va.y = pk2(-2.0f * b0, -2.0f * b1);
            vb.x = pk2(-2.0f * c0, -2.0f * c1);
            vb.y = pk2(rr0, rr1);
            s_a[j] = va;
            s_b[j] = vb;
        }
        __syncthreads();

#pragma unroll 4
        for (int j = 0; j < J2; j++) {
            ulonglong2 va = s_a[j];
            ulonglong2 vb = s_b[j];
#pragma unroll
            for (int k = 0; k < IPT; k++) {
                unsigned long long d =
                    fma2(qx2[k], va.x, fma2(qy2[k], va.y, fma2(qz2[k], vb.x, vb.y)));
                float dl, dh;
                upk2(d, dl, dh);
                mnl[k] = fminf(mnl[k], dl);
                mnh[k] = fminf(mnh[k], dh);
            }
        }
    }

    float local = 0.0f;
#pragma unroll
    for (int k = 0; k < IPT; k++)
        local += rq[k] + fminf(mnl[k], mnh[k]);

    // warp + block reduce
#pragma unroll
    for (int o = 16; o > 0; o >>= 1)
        local += __shfl_xor_sync(0xffffffffu, local, o);
    if ((tid & 31) == 0) ws[tid >> 5] = local;
    __syncthreads();

    if (tid == 0) {
        float s = 0.0f;
#pragma unroll
        for (int w = 0; w < THREADS / 32; w++) s += ws[w];
        atomicAdd(&g_acc, s);
        __threadfence();
        unsigned int arrived = atomicAdd(&g_count, 1u);
        if (arrived == GRID - 1) {
            __threadfence();
            float total = *((volatile float*)&g_acc);
            out[0] = total * (1.0f / (float)(BATCH * NPTS));
            g_acc   = 0.0f;    // restore invariant for next replay
            g_count = 0u;
        }
    }
}

extern "C" void kernel_launch(void* const* d_in, const int* in_sizes, int n_in,
                              void* d_out, int out_size) {
    const float* x = (const float*)d_in[0];
    const float* y = (const float*)d_in[1];
    float* out = (float*)d_out;
    (void)in_sizes; (void)n_in; (void)out_size;

    k_chamfer<<<GRID, THREADS>>>(x, y, out);
}

// round 6
// speedup vs baseline: 1.1453x; 1.1453x over previous
#include <cuda_runtime.h>
#include <cstdint>

// Chamfer loss, fused single kernel. B=16, N=4096, C=6 (first 3 used).
// d(i,j) = |q_i|^2 + [ |r_j|^2 - 2 q_i . r_j ]
// Ref tile prescaled to (-2r0,-2r1,-2r2,|r|^2): 3 packed FFMA2 per 2 pairs.
// R4: GRID=128 x THREADS=512, IPT=2 -> 16 warps/SM (4/SMSP) for latency hiding.

#define BATCH 16
#define NPTS  4096
#define CSTR  6
#define THREADS 512
#define IPT 2             // query points per thread
#define JT  2048          // ref points per smem tile
#define J2  (JT / 2)
#define GRID 128          // 2*16*4096 / (THREADS*IPT); one CTA per SM, single wave

__device__ float        g_acc;    // zero-init; reset by last CTA each launch
__device__ unsigned int g_count;  // zero-init; reset by last CTA each launch

__device__ __forceinline__ unsigned long long pk2(float lo, float hi) {
    unsigned long long r;
    asm("mov.b64 %0, {%1, %2};" : "=l"(r) : "f"(lo), "f"(hi));
    return r;
}
__device__ __forceinline__ unsigned long long fma2(unsigned long long a,
                                                   unsigned long long b,
                                                   unsigned long long c) {
    unsigned long long d;
    asm("fma.rn.f32x2 %0, %1, %2, %3;" : "=l"(d) : "l"(a), "l"(b), "l"(c));
    return d;
}
__device__ __forceinline__ void upk2(unsigned long long v, float& lo, float& hi) {
    asm("mov.b64 {%0, %1}, %2;" : "=f"(lo), "=f"(hi) : "l"(v));
}

__global__ void __launch_bounds__(THREADS)
k_chamfer(const float* __restrict__ x, const float* __restrict__ y,
          float* __restrict__ out) {
    __shared__ ulonglong2 s_a[J2];   // {-2rx pair}, {-2ry pair}
    __shared__ ulonglong2 s_b[J2];   // {-2rz pair}, {rr pair}
    __shared__ float ws[THREADS / 32];

    const int bid  = blockIdx.x;      // 0..127
    const int dir  = bid >> 6;        // 0: q=x,r=y ; 1: q=y,r=x
    const int t    = bid & 63;
    const int b    = t >> 2;          // batch
    const int tile = t & 3;           // i-tile (4 tiles of 1024 queries)

    const float* q  = dir ? y : x;
    const float* r  = dir ? x : y;
    const float* qb = q + (size_t)b * NPTS * CSTR;
    const float* rb = r + (size_t)b * NPTS * CSTR;

    const int tid = threadIdx.x;

    unsigned long long qx2[IPT], qy2[IPT], qz2[IPT];
    float rq[IPT], mnl[IPT], mnh[IPT];
    const int i0 = tile * (THREADS * IPT) + tid * IPT;
#pragma unroll
    for (int k = 0; k < IPT; k++) {
        const float* p = qb + (size_t)(i0 + k) * CSTR;
        float a = p[0], bb = p[1], c = p[2];
        rq[k]  = fmaf(a, a, fmaf(bb, bb, c * c));
        qx2[k] = pk2(a, a);
        qy2[k] = pk2(bb, bb);
        qz2[k] = pk2(c, c);
        mnl[k] = 3.4e38f;
        mnh[k] = 3.4e38f;
    }

    for (int jc = 0; jc < NPTS; jc += JT) {
        __syncthreads();
        for (int j = tid; j < J2; j += THREADS) {
            const float* p = rb + (size_t)(jc + 2 * j) * CSTR;
            float a0 = p[0], b0 = p[1], c0 = p[2];
            float a1 = p[6], b1 = p[7], c1 = p[8];
            float rr0 = fmaf(a0, a0, fmaf(b0, b0, c0 * c0));
            float rr1 = fmaf(a1, a1, fmaf(b1, b1, c1 * c1));
            ulonglong2 va, vb;
            va.x = pk2(-2.0f * a0, -2.0f * a1);
            va.y = pk2(-2.0f * b0, -2.0f * b1);
            vb.x = pk2(-2.0f * c0, -2.0f * c1);
            vb.y = pk2(rr0, rr1);
            s_a[j] = va;
            s_b[j] = vb;
        }
        __syncthreads();

#pragma unroll 8
        for (int j = 0; j < J2; j++) {
            ulonglong2 va = s_a[j];
            ulonglong2 vb = s_b[j];
#pragma unroll
            for (int k = 0; k < IPT; k++) {
                unsigned long long d =
                    fma2(qx2[k], va.x, fma2(qy2[k], va.y, fma2(qz2[k], vb.x, vb.y)));
                float dl, dh;
                upk2(d, dl, dh);
                mnl[k] = fminf(mnl[k], dl);
                mnh[k] = fminf(mnh[k], dh);
            }
        }
    }

    float local = 0.0f;
#pragma unroll
    for (int k = 0; k < IPT; k++)
        local += rq[k] + fminf(mnl[k], mnh[k]);

    // warp + block reduce
#pragma unroll
    for (int o = 16; o > 0; o >>= 1)
        local += __shfl_xor_sync(0xffffffffu, local, o);
    if ((tid & 31) == 0) ws[tid >> 5] = local;
    __syncthreads();

    if (tid == 0) {
        float s = 0.0f;
#pragma unroll
        for (int w = 0; w < THREADS / 32; w++) s += ws[w];
        atomicAdd(&g_acc, s);
        __threadfence();
        unsigned int arrived = atomicAdd(&g_count, 1u);
        if (arrived == GRID - 1) {
            __threadfence();
            float total = *((volatile float*)&g_acc);
            out[0] = total * (1.0f / (float)(BATCH * NPTS));
            g_acc   = 0.0f;    // restore invariant for next replay
            g_count = 0u;
        }
    }
}

extern "C" void kernel_launch(void* const* d_in, const int* in_sizes, int n_in,
                              void* d_out, int out_size) {
    const float* x = (const float*)d_in[0];
    const float* y = (const float*)d_in[1];
    float* out = (float*)d_out;
    (void)in_sizes; (void)n_in; (void)out_size;

    k_chamfer<<<GRID, THREADS>>>(x, y, out);
}